// round 12
// baseline (speedup 1.0000x reference)
#include <cuda_runtime.h>
#include <cuda_fp16.h>
#include <cstdint>

#define ZS 512
#define MM 512
#define HHN 511
#define NB 65536

__device__ float g_vn[512 * ZS];                      // padded: row 511 = 0
__device__ float g_q [ZS * MM];
__device__ float g_T [128 * 16];                      // WY T (4x4) per 4-block
__device__ float g_rrii[MM];
__device__ float g_r1d [MM * MM];                     // dense r1[k][j]
__device__ float g_r2Td[MM * MM];                     // dense r2^T[k][j] = r2[j][k]
__device__ half g_Af  [ZS * MM];                      // A[z][m] single fp16
__device__ half g_Bthi[MM * ZS], g_Btlo[MM * ZS];     // Bt^T[m][z] fp16 hi/lo
__device__ half g_zhi [(size_t)NB * ZS], g_zlo[(size_t)NB * ZS];
__device__ half g_hbf [(size_t)NB * MM];              // tanh(...) single fp16

__device__ __forceinline__ uint32_t smem_u32(const void* p) {
    uint32_t a;
    asm("{ .reg .u64 t; cvta.to.shared.u64 t, %1; cvt.u32.u64 %0, t; }" : "=r"(a) : "l"(p));
    return a;
}
__device__ __forceinline__ void cpa16(uint32_t s, const void* g) {
    asm volatile("cp.async.cg.shared.global [%0], [%1], 16;" :: "r"(s), "l"(g) : "memory");
}
#define CP_COMMIT() asm volatile("cp.async.commit_group;" ::: "memory")
#define CP_WAIT0()  asm volatile("cp.async.wait_group 0;" ::: "memory")
#define CP_WAIT1()  asm volatile("cp.async.wait_group 1;" ::: "memory")
#define CP_WAIT2()  asm volatile("cp.async.wait_group 2;" ::: "memory")

__device__ __forceinline__ void ldsm4(uint32_t addr, uint32_t* r) {
    asm volatile("ldmatrix.sync.aligned.m8n8.x4.shared.b16 {%0,%1,%2,%3}, [%4];"
        : "=r"(r[0]), "=r"(r[1]), "=r"(r[2]), "=r"(r[3]) : "r"(addr));
}
__device__ __forceinline__ void mma16816(float* d, const uint32_t* a, const uint32_t* b) {
    asm volatile("mma.sync.aligned.m16n8k16.row.col.f32.f16.f16.f32 "
        "{%0,%1,%2,%3}, {%4,%5,%6,%7}, {%8,%9}, {%0,%1,%2,%3};"
        : "+f"(d[0]), "+f"(d[1]), "+f"(d[2]), "+f"(d[3])
        : "r"(a[0]), "r"(a[1]), "r"(a[2]), "r"(a[3]), "r"(b[0]), "r"(b[1]));
}
__device__ __forceinline__ void mma16816h(uint32_t* d, const uint32_t* a, const uint32_t* b) {
    asm volatile("mma.sync.aligned.m16n8k16.row.col.f16.f16.f16.f16 "
        "{%0,%1}, {%2,%3,%4,%5}, {%6,%7}, {%0,%1};"
        : "+r"(d[0]), "+r"(d[1])
        : "r"(a[0]), "r"(a[1]), "r"(a[2]), "r"(a[3]), "r"(b[0]), "r"(b[1]));
}

#define STG1 32768
#define SMEM1 (3 * STG1)
#define STG2 16384
#define SMEM2 (4 * STG2)

// ---------------- normalize + init + densify r1/r2T ----------------
__global__ void normalize_kernel(const float* __restrict__ v, const float* __restrict__ Rs,
                                 const float* __restrict__ r2diag, float* __restrict__ ldj) {
    int row = blockIdx.x, tid = threadIdx.x;
    int gidx = blockIdx.x * 256 + tid;
    if (gidx < NB) ldj[gidx] = 0.f;
    if (gidx < MM) g_rrii[gidx] = Rs[(size_t)gidx * MM + gidx] * r2diag[gidx];
    // densify: k = row
    #pragma unroll
    for (int l = 0; l < 2; l++) {
        int j = tid + l * 256;
        g_r1d [(size_t)row * MM + j] = (row <= j) ? Rs[(size_t)row * MM + j] : 0.f;
        g_r2Td[(size_t)row * MM + j] =
            (row > j) ? Rs[(size_t)j * MM + row] : ((row == j) ? r2diag[j] : 0.f);
    }
    if (row < HHN) {
        float a = v[row * ZS + tid], b = v[row * ZS + tid + 256];
        float s = a * a + b * b;
        #pragma unroll
        for (int o = 16; o > 0; o >>= 1) s += __shfl_xor_sync(0xffffffffu, s, o);
        __shared__ float ws[8];
        if ((tid & 31) == 0) ws[tid >> 5] = s;
        __syncthreads();
        float inv = rsqrtf(ws[0]+ws[1]+ws[2]+ws[3]+ws[4]+ws[5]+ws[6]+ws[7]);
        g_vn[row * ZS + tid] = a * inv;
        g_vn[row * ZS + tid + 256] = b * inv;
    } else if (row == HHN) {
        g_vn[row * ZS + tid] = 0.f;
        g_vn[row * ZS + tid + 256] = 0.f;
    }
}

// ---------------- WY T build ----------------
__global__ void tbuild_kernel() {
    __shared__ float cs[4][4];
    int tid = threadIdx.x, w = tid >> 5, lane = tid & 31, b = blockIdx.x;
    const int pi[6] = {0,0,0,1,1,2}, pj[6] = {1,2,3,2,3,3};
    if (w < 6) {
        const float* vi = g_vn + (size_t)(b * 4 + pi[w]) * ZS;
        const float* vj = g_vn + (size_t)(b * 4 + pj[w]) * ZS;
        float s = 0.f;
        #pragma unroll
        for (int t = 0; t < 16; t++) s += vi[lane + 32 * t] * vj[lane + 32 * t];
        #pragma unroll
        for (int o = 16; o > 0; o >>= 1) s += __shfl_xor_sync(0xffffffffu, s, o);
        if (lane == 0) cs[pi[w]][pj[w]] = s;
    }
    __syncthreads();
    if (tid == 0) {
        float T[4][4] = {};
        T[0][0] = T[1][1] = T[2][2] = T[3][3] = 2.f;
        for (int k = 1; k < 4; k++)
            for (int i = 0; i < k; i++) {
                float s = 0.f;
                for (int j = i; j < k; j++) s += T[i][j] * cs[j][k];
                T[i][k] = -2.f * s;
            }
        for (int i = 0; i < 4; i++)
            for (int k = 0; k < 4; k++) g_T[b * 16 + i * 4 + k] = T[i][k];
    }
}

// ---------------- fused: scan (blocks 0..63) + zsplit (blocks 64..) ----------------
__global__ void __launch_bounds__(128, 2) scan_zsplit_kernel(const float* __restrict__ z) {
    __shared__ float sv[2][4 * 512];
    __shared__ float Ts[2][16];
    int tid = threadIdx.x;
    if (blockIdx.x >= 64) {   // ---- zsplit: fp32 -> fp16 hi/lo ----
        size_t u = (((size_t)(blockIdx.x - 64)) * 128 + tid) * 8;
        const float4* zp = (const float4*)(z + u);
        float4 a = zp[0], b = zp[1];
        float vs[8] = {a.x,a.y,a.z,a.w,b.x,b.y,b.z,b.w};
        half hi[8], lo[8];
        #pragma unroll
        for (int e = 0; e < 8; e++) {
            hi[e] = __float2half_rn(vs[e]);
            lo[e] = __float2half_rn(vs[e] - __half2float(hi[e]));
        }
        *(uint4*)&g_zhi[u] = *(uint4*)hi;
        *(uint4*)&g_zlo[u] = *(uint4*)lo;
        return;
    }
    // ---- scan ----
    int lane = tid & 31, warp = tid >> 5;
    int r0 = blockIdx.x * 8 + warp * 2;
    float f0[16], f1[16];
    #pragma unroll
    for (int j = 0; j < 16; j++) {
        int col = (j >> 2) * 128 + lane * 4 + (j & 3);
        f0[j] = (col == r0) ? 1.f : 0.f;
        f1[j] = (col == r0 + 1) ? 1.f : 0.f;
    }
    #pragma unroll
    for (int q = 0; q < 4; q++)
        *(float4*)&sv[0][(q * 128 + tid) * 4] = *(const float4*)&g_vn[(q * 128 + tid) * 4];
    if (tid < 16) Ts[0][tid] = g_T[tid];
    __syncthreads();

    for (int blk = 0; blk < 128; blk++) {
        int cur = blk & 1, nxt = cur ^ 1;
        float4 pf[4]; float tpf = 0.f;
        bool more = (blk + 1 < 128);
        if (more) {
            #pragma unroll
            for (int q = 0; q < 4; q++)
                pf[q] = *(const float4*)&g_vn[(size_t)(blk + 1) * 2048 + (q * 128 + tid) * 4];
            if (tid < 16) tpf = g_T[(blk + 1) * 16 + tid];
        }
        float vv[4][16];
        #pragma unroll
        for (int vb = 0; vb < 4; vb++)
            #pragma unroll
            for (int q = 0; q < 4; q++) {
                float4 t = *(const float4*)&sv[cur][vb * 512 + q * 128 + lane * 4];
                vv[vb][q*4+0] = t.x; vv[vb][q*4+1] = t.y; vv[vb][q*4+2] = t.z; vv[vb][q*4+3] = t.w;
            }
        float d0[4] = {}, d1[4] = {};
        #pragma unroll
        for (int vb = 0; vb < 4; vb++)
            #pragma unroll
            for (int j = 0; j < 16; j++) {
                d0[vb] = fmaf(f0[j], vv[vb][j], d0[vb]);
                d1[vb] = fmaf(f1[j], vv[vb][j], d1[vb]);
            }
        #pragma unroll
        for (int o = 16; o > 0; o >>= 1)
            #pragma unroll
            for (int vb = 0; vb < 4; vb++) {
                d0[vb] += __shfl_xor_sync(0xffffffffu, d0[vb], o);
                d1[vb] += __shfl_xor_sync(0xffffffffu, d1[vb], o);
            }
        float w0[4], w1[4];
        #pragma unroll
        for (int k = 0; k < 4; k++) {
            float s0 = 0.f, s1 = 0.f;
            #pragma unroll
            for (int i = 0; i < 4; i++) {
                if (i <= k) {
                    float t = Ts[cur][i * 4 + k];
                    s0 = fmaf(d0[i], t, s0);
                    s1 = fmaf(d1[i], t, s1);
                }
            }
            w0[k] = s0; w1[k] = s1;
        }
        #pragma unroll
        for (int j = 0; j < 16; j++) {
            float a0 = f0[j], a1 = f1[j];
            #pragma unroll
            for (int vb = 0; vb < 4; vb++) {
                a0 = fmaf(-w0[vb], vv[vb][j], a0);
                a1 = fmaf(-w1[vb], vv[vb][j], a1);
            }
            f0[j] = a0; f1[j] = a1;
        }
        if (more) {
            #pragma unroll
            for (int q = 0; q < 4; q++)
                *(float4*)&sv[nxt][(q * 128 + tid) * 4] = pf[q];
            if (tid < 16) Ts[nxt][tid] = tpf;
        }
        __syncthreads();
    }
    #pragma unroll
    for (int q = 0; q < 4; q++) {
        *(float4*)&g_q[(size_t)r0 * ZS + q * 128 + lane * 4] = make_float4(f0[q*4], f0[q*4+1], f0[q*4+2], f0[q*4+3]);
        *(float4*)&g_q[(size_t)(r0 + 1) * ZS + q * 128 + lane * 4] = make_float4(f1[q*4], f1[q*4+1], f1[q*4+2], f1[q*4+3]);
    }
}

// small GEMMs (dense, pipelined). mode0: A=q@r1d -> g_Af; mode1: (q@r2^T)^T = r2Td-GEMM -> g_Bthi/lo
__global__ void __launch_bounds__(256) small_gemm_kernel() {
    __shared__ float Qs[2][16][68], Bs[2][16][68];
    int tid = threadIdx.x, tx = tid & 15, ty = tid >> 4;
    int j0 = blockIdx.x * 64, i0 = blockIdx.y * 64, mode = blockIdx.z;
    const float* Bsrc = mode ? g_r2Td : g_r1d;
    int qi = tid >> 2, qk = tid & 3;          // Q loader: row i, k-quad
    int bk = tid >> 4, bq = tid & 15;         // B loader: row k, 16B chunk
    uint32_t bdst0 = smem_u32(&Bs[0][bk][bq * 4]);
    uint32_t bstride = (uint32_t)(sizeof(float) * 16 * 68);
    float acc[4][4] = {};

    // prologue: kt = 0
    float4 qv = *(const float4*)&g_q[(size_t)(i0 + qi) * ZS + qk * 4];
    cpa16(bdst0, Bsrc + (size_t)bk * MM + j0 + bq * 4);
    CP_COMMIT();
    Qs[0][qk*4+0][qi] = qv.x; Qs[0][qk*4+1][qi] = qv.y;
    Qs[0][qk*4+2][qi] = qv.z; Qs[0][qk*4+3][qi] = qv.w;

    for (int kt = 0; kt < 32; kt++) {
        int cur = kt & 1, nxt = cur ^ 1;
        bool more = (kt + 1 < 32);
        float4 qn;
        if (more)
            qn = *(const float4*)&g_q[(size_t)(i0 + qi) * ZS + (kt + 1) * 16 + qk * 4];
        CP_WAIT0();
        __syncthreads();
        if (more) {
            cpa16(bdst0 + nxt * bstride, Bsrc + (size_t)((kt + 1) * 16 + bk) * MM + j0 + bq * 4);
            CP_COMMIT();
        }
        #pragma unroll
        for (int kk = 0; kk < 16; kk++) {
            float4 a4 = *(const float4*)&Qs[cur][kk][ty * 4];
            float4 b4 = *(const float4*)&Bs[cur][kk][tx * 4];
            const float a[4] = {a4.x, a4.y, a4.z, a4.w};
            const float b[4] = {b4.x, b4.y, b4.z, b4.w};
            #pragma unroll
            for (int x = 0; x < 4; x++)
                #pragma unroll
                for (int y = 0; y < 4; y++) acc[x][y] = fmaf(a[x], b[y], acc[x][y]);
        }
        if (more) {
            Qs[nxt][qk*4+0][qi] = qn.x; Qs[nxt][qk*4+1][qi] = qn.y;
            Qs[nxt][qk*4+2][qi] = qn.z; Qs[nxt][qk*4+3][qi] = qn.w;
        }
    }
    #pragma unroll
    for (int x = 0; x < 4; x++)
        #pragma unroll
        for (int y = 0; y < 4; y++) {
            int i = i0 + ty*4 + x, j = j0 + tx*4 + y;
            float val = acc[x][y];
            half h = __float2half_rn(val);
            if (mode == 0) {
                g_Af[(size_t)i * MM + j] = h;
            } else {
                g_Bthi[(size_t)j * ZS + i] = h;
                g_Btlo[(size_t)j * ZS + i] = __float2half_rn(val - __half2float(h));
            }
        }
}

// ---------------- GEMM1 mainloop: main pass f32-acc, 2 correction passes f16-acc ----------------
__device__ __forceinline__ void load_stage1(uint32_t sbuf,
    const half* __restrict__ Ah, const half* __restrict__ Al,
    const half* __restrict__ Bh, const half* __restrict__ Bl,
    int m0, int n0, int ch, int tid) {
    #pragma unroll
    for (int q = 0; q < 8; q++) {
        int idx = ((q & 1) << 8) + tid;
        int m = idx >> 2, cc2 = idx & 3;
        int slab = cc2 >> 1, hf = cc2 & 1;
        uint32_t dst = sbuf + (q >> 1) * 8192 + slab * 4096 + m * 32
                     + ((hf ^ ((m >> 2) & 1)) << 4);
        const half* base = (q < 2) ? Ah : (q < 4) ? Al : (q < 6) ? Bh : Bl;
        int row0 = (q < 4) ? m0 : n0;
        cpa16(dst, base + (size_t)(row0 + m) * 512 + ch * 32 + slab * 16 + hf * 8);
    }
}

__device__ __forceinline__ void mainloop3(float (&acc)[2][8][4], uint32_t (&cacc)[2][8][2],
    const half* __restrict__ Ah, const half* __restrict__ Al,
    const half* __restrict__ Bh, const half* __restrict__ Bl,
    int m0, int n0, uint32_t sb, int tid) {
    int lane = tid & 31, wid = tid >> 5;
    int wm = wid & 3, wn = wid >> 2;
    int arow = (lane & 7) + ((lane >> 3) & 1) * 8;
    int akh  = (lane >> 4) & 1;
    uint32_t aoff = (uint32_t)((wm * 32 + arow) * 32) + ((akh ^ ((arow >> 2) & 1)) << 4);
    int brow = (lane & 7) + ((lane >> 4) & 1) * 8;
    int bkh  = (lane >> 3) & 1;
    uint32_t boff = 16384u + (uint32_t)((wn * 64 + brow) * 32) + ((bkh ^ ((brow >> 2) & 1)) << 4);

    load_stage1(sb,        Ah, Al, Bh, Bl, m0, n0, 0, tid); CP_COMMIT();
    load_stage1(sb + STG1, Ah, Al, Bh, Bl, m0, n0, 1, tid); CP_COMMIT();

    for (int ch = 0; ch < 16; ch++) {
        CP_WAIT1();
        __syncthreads();
        if (ch + 2 < 16)
            load_stage1(sb + ((ch + 2) % 3) * STG1, Ah, Al, Bh, Bl, m0, n0, ch + 2, tid);
        CP_COMMIT();
        uint32_t st = sb + (ch % 3) * STG1;
        #pragma unroll
        for (int slab = 0; slab < 2; slab++) {
            uint32_t sB = st + slab * 4096;
            uint32_t ah[2][4], al[2][4], bh[4][4], bl[4][4];
            ldsm4(sB + aoff,        ah[0]);
            ldsm4(sB + aoff + 512,  ah[1]);
            #pragma unroll
            for (int p = 0; p < 4; p++) ldsm4(sB + boff + p * 512, bh[p]);
            ldsm4(sB + 8192 + aoff,       al[0]);
            ldsm4(sB + 8192 + aoff + 512, al[1]);
            #pragma unroll
            for (int mt = 0; mt < 2; mt++)
                #pragma unroll
                for (int nt = 0; nt < 8; nt++)
                    mma16816(acc[mt][nt], ah[mt], &bh[nt >> 1][(nt & 1) * 2]);
            #pragma unroll
            for (int p = 0; p < 4; p++) ldsm4(sB + 8192 + boff + p * 512, bl[p]);
            #pragma unroll
            for (int mt = 0; mt < 2; mt++)
                #pragma unroll
                for (int nt = 0; nt < 8; nt++)
                    mma16816h(cacc[mt][nt], al[mt], &bh[nt >> 1][(nt & 1) * 2]);
            #pragma unroll
            for (int mt = 0; mt < 2; mt++)
                #pragma unroll
                for (int nt = 0; nt < 8; nt++)
                    mma16816h(cacc[mt][nt], ah[mt], &bl[nt >> 1][(nt & 1) * 2]);
        }
    }
}

// ---------------- GEMM2 mainloop: single-pass fp16 ----------------
__device__ __forceinline__ void load_stage2(uint32_t sbuf,
    const half* __restrict__ A, const half* __restrict__ B,
    int m0, int n0, int ch, int tid) {
    #pragma unroll
    for (int q = 0; q < 4; q++) {
        int idx = ((q & 1) << 8) + tid;
        int m = idx >> 2, cc2 = idx & 3;
        int slab = cc2 >> 1, hf = cc2 & 1;
        uint32_t dst = sbuf + (q >> 1) * 8192 + slab * 4096 + m * 32
                     + ((hf ^ ((m >> 2) & 1)) << 4);
        const half* base = (q < 2) ? A : B;
        int row0 = (q < 2) ? m0 : n0;
        cpa16(dst, base + (size_t)(row0 + m) * 512 + ch * 32 + slab * 16 + hf * 8);
    }
}

__device__ __forceinline__ void mainloop1(float (&acc)[2][8][4],
    const half* __restrict__ A, const half* __restrict__ B,
    int m0, int n0, uint32_t sb, int tid) {
    int lane = tid & 31, wid = tid >> 5;
    int wm = wid & 3, wn = wid >> 2;
    int arow = (lane & 7) + ((lane >> 3) & 1) * 8;
    int akh  = (lane >> 4) & 1;
    uint32_t aoff = (uint32_t)((wm * 32 + arow) * 32) + ((akh ^ ((arow >> 2) & 1)) << 4);
    int brow = (lane & 7) + ((lane >> 4) & 1) * 8;
    int bkh  = (lane >> 3) & 1;
    uint32_t boff = 8192u + (uint32_t)((wn * 64 + brow) * 32) + ((bkh ^ ((brow >> 2) & 1)) << 4);

    load_stage2(sb,            A, B, m0, n0, 0, tid); CP_COMMIT();
    load_stage2(sb + STG2,     A, B, m0, n0, 1, tid); CP_COMMIT();
    load_stage2(sb + 2 * STG2, A, B, m0, n0, 2, tid); CP_COMMIT();

    for (int ch = 0; ch < 16; ch++) {
        CP_WAIT2();
        __syncthreads();
        if (ch + 3 < 16) {
            load_stage2(sb + ((ch + 3) & 3) * STG2, A, B, m0, n0, ch + 3, tid);
            CP_COMMIT();
        }
        uint32_t st = sb + (ch & 3) * STG2;
        #pragma unroll
        for (int slab = 0; slab < 2; slab++) {
            uint32_t sB = st + slab * 4096;
            uint32_t ah[2][4], bh[4][4];
            ldsm4(sB + aoff,       ah[0]);
            ldsm4(sB + aoff + 512, ah[1]);
            #pragma unroll
            for (int p = 0; p < 4; p++) ldsm4(sB + boff + p * 512, bh[p]);
            #pragma unroll
            for (int mt = 0; mt < 2; mt++)
                #pragma unroll
                for (int nt = 0; nt < 8; nt++)
                    mma16816(acc[mt][nt], ah[mt], &bh[nt >> 1][(nt & 1) * 2]);
        }
    }
}

// GEMM1: hB = tanh(z@Bt + c), ldj, emit hB fp16
__global__ void __launch_bounds__(256, 1) gemm1_kernel(const float* __restrict__ c,
                                                       float* __restrict__ ldj) {
    extern __shared__ char smem[];
    uint32_t sb = smem_u32(smem);
    int tid = threadIdx.x, lane = tid & 31, wid = tid >> 5;
    int wm = wid & 3, wn = wid >> 2;
    int n0 = blockIdx.x * 128, m0 = blockIdx.y * 128;
    float acc[2][8][4] = {};
    uint32_t cacc[2][8][2] = {};
    mainloop3(acc, cacc, g_zhi, g_zlo, g_Bthi, g_Btlo, m0, n0, sb, tid);

    float cc[16], rr[16];
    #pragma unroll
    for (int nt = 0; nt < 8; nt++) {
        int col = n0 + wn * 64 + nt * 8 + (lane & 3) * 2;
        cc[nt*2] = c[col]; cc[nt*2+1] = c[col+1];
        rr[nt*2] = g_rrii[col]; rr[nt*2+1] = g_rrii[col+1];
    }
    #pragma unroll
    for (int mt = 0; mt < 2; mt++) {
        int row = m0 + wm * 32 + mt * 16 + (lane >> 2);
        float s0 = 0.f, s1 = 0.f;
        #pragma unroll
        for (int nt = 0; nt < 8; nt++) {
            int col = n0 + wn * 64 + nt * 8 + (lane & 3) * 2;
            half2 c0 = *(half2*)&cacc[mt][nt][0];
            half2 c1 = *(half2*)&cacc[mt][nt][1];
            float h00 = tanhf(acc[mt][nt][0] + __half2float(c0.x) + cc[nt*2]);
            float h01 = tanhf(acc[mt][nt][1] + __half2float(c0.y) + cc[nt*2+1]);
            float h10 = tanhf(acc[mt][nt][2] + __half2float(c1.x) + cc[nt*2]);
            float h11 = tanhf(acc[mt][nt][3] + __half2float(c1.y) + cc[nt*2+1]);
            *(half2*)&g_hbf[(size_t)row * MM + col]       = __floats2half2_rn(h00, h01);
            *(half2*)&g_hbf[(size_t)(row + 8) * MM + col] = __floats2half2_rn(h10, h11);
            s0 += __logf(fabsf(fmaf(1.f - h00*h00, rr[nt*2],   1.f)));
            s0 += __logf(fabsf(fmaf(1.f - h01*h01, rr[nt*2+1], 1.f)));
            s1 += __logf(fabsf(fmaf(1.f - h10*h10, rr[nt*2],   1.f)));
            s1 += __logf(fabsf(fmaf(1.f - h11*h11, rr[nt*2+1], 1.f)));
        }
        s0 += __shfl_xor_sync(0xffffffffu, s0, 1); s0 += __shfl_xor_sync(0xffffffffu, s0, 2);
        s1 += __shfl_xor_sync(0xffffffffu, s1, 1); s1 += __shfl_xor_sync(0xffffffffu, s1, 2);
        if ((lane & 3) == 0) {
            atomicAdd(&ldj[row], s0);
            atomicAdd(&ldj[row + 8], s1);
        }
    }
}

// GEMM2: out = hB @ A^T + z
__global__ void __launch_bounds__(256, 2) gemm2_kernel(const float* __restrict__ z,
                                                       float* __restrict__ out) {
    extern __shared__ char smem[];
    uint32_t sb = smem_u32(smem);
    int tid = threadIdx.x, lane = tid & 31, wid = tid >> 5;
    int wm = wid & 3, wn = wid >> 2;
    int n0 = blockIdx.x * 128, m0 = blockIdx.y * 128;
    float acc[2][8][4] = {};
    mainloop1(acc, g_hbf, g_Af, m0, n0, sb, tid);

    #pragma unroll
    for (int mt = 0; mt < 2; mt++) {
        int row = m0 + wm * 32 + mt * 16 + (lane >> 2);
        #pragma unroll
        for (int nt = 0; nt < 8; nt++) {
            int col = n0 + wn * 64 + nt * 8 + (lane & 3) * 2;
            float2 z0 = *(const float2*)&z[(size_t)row * ZS + col];
            float2 z1 = *(const float2*)&z[(size_t)(row + 8) * ZS + col];
            *(float2*)&out[(size_t)row * ZS + col] =
                make_float2(acc[mt][nt][0] + z0.x, acc[mt][nt][1] + z0.y);
            *(float2*)&out[(size_t)(row + 8) * ZS + col] =
                make_float2(acc[mt][nt][2] + z1.x, acc[mt][nt][3] + z1.y);
        }
    }
}

// ---------------- launch ----------------
extern "C" void kernel_launch(void* const* d_in, const int* in_sizes, int n_in,
                              void* d_out, int out_size) {
    const float* z      = (const float*)d_in[0];
    const float* v      = (const float*)d_in[1];
    const float* Rs     = (const float*)d_in[2];
    const float* r2diag = (const float*)d_in[3];
    const float* c      = (const float*)d_in[4];
    float* out = (float*)d_out;
    float* ldj = out + (size_t)NB * ZS;

    cudaFuncSetAttribute(gemm1_kernel, cudaFuncAttributeMaxDynamicSharedMemorySize, SMEM1);
    cudaFuncSetAttribute(gemm2_kernel, cudaFuncAttributeMaxDynamicSharedMemorySize, SMEM2);

    normalize_kernel<<<512, 256>>>(v, Rs, r2diag, ldj);
    tbuild_kernel<<<128, 192>>>();
    scan_zsplit_kernel<<<64 + (int)((size_t)NB * ZS / 1024), 128>>>(z);
    small_gemm_kernel<<<dim3(8, 8, 2), 256>>>();
    gemm1_kernel<<<dim3(4, 512), 256, SMEM1>>>(c, ldj);
    gemm2_kernel<<<dim3(4, 512), 256, SMEM2>>>(z, out);
}

// round 13
// speedup vs baseline: 1.0249x; 1.0249x over previous
#include <cuda_runtime.h>
#include <cuda_fp16.h>
#include <cstdint>

#define ZS 512
#define MM 512
#define HHN 511
#define NB 65536

__device__ float g_vn[512 * ZS];                      // padded: row 511 = 0
__device__ float g_q [ZS * MM];
__device__ float g_T [128 * 16];                      // WY T (4x4) per 4-block
__device__ float g_rrii[MM];
__device__ float g_r1d [MM * MM];                     // dense r1[k][j]
__device__ float g_r2Td[MM * MM];                     // dense r2^T[k][j]
__device__ half g_Af  [ZS * MM];                      // A[z][m] single fp16
__device__ half g_Bthi[MM * ZS], g_Btlo[MM * ZS];     // Bt^T[m][z] fp16 hi/lo
__device__ half g_zhi [(size_t)NB * ZS], g_zlo[(size_t)NB * ZS];
__device__ half g_hbf [(size_t)NB * MM];              // tanh(...) single fp16

__device__ __forceinline__ uint32_t smem_u32(const void* p) {
    uint32_t a;
    asm("{ .reg .u64 t; cvta.to.shared.u64 t, %1; cvt.u32.u64 %0, t; }" : "=r"(a) : "l"(p));
    return a;
}
__device__ __forceinline__ void cpa16(uint32_t s, const void* g) {
    asm volatile("cp.async.cg.shared.global [%0], [%1], 16;" :: "r"(s), "l"(g) : "memory");
}
#define CP_COMMIT() asm volatile("cp.async.commit_group;" ::: "memory")
#define CP_WAIT0()  asm volatile("cp.async.wait_group 0;" ::: "memory")
#define CP_WAIT1()  asm volatile("cp.async.wait_group 1;" ::: "memory")
#define CP_WAIT2()  asm volatile("cp.async.wait_group 2;" ::: "memory")

__device__ __forceinline__ void ldsm4(uint32_t addr, uint32_t* r) {
    asm volatile("ldmatrix.sync.aligned.m8n8.x4.shared.b16 {%0,%1,%2,%3}, [%4];"
        : "=r"(r[0]), "=r"(r[1]), "=r"(r[2]), "=r"(r[3]) : "r"(addr));
}
__device__ __forceinline__ void mma16816(float* d, const uint32_t* a, const uint32_t* b) {
    asm volatile("mma.sync.aligned.m16n8k16.row.col.f32.f16.f16.f32 "
        "{%0,%1,%2,%3}, {%4,%5,%6,%7}, {%8,%9}, {%0,%1,%2,%3};"
        : "+f"(d[0]), "+f"(d[1]), "+f"(d[2]), "+f"(d[3])
        : "r"(a[0]), "r"(a[1]), "r"(a[2]), "r"(a[3]), "r"(b[0]), "r"(b[1]));
}

#define STG1 49152
#define SMEM1 (3 * STG1)
#define STG2 24576
#define SMEM2 (4 * STG2)

// ---------------- normalize + init + densify r1/r2T ----------------
__global__ void normalize_kernel(const float* __restrict__ v, const float* __restrict__ Rs,
                                 const float* __restrict__ r2diag, float* __restrict__ ldj) {
    int row = blockIdx.x, tid = threadIdx.x;
    int gidx = blockIdx.x * 256 + tid;
    if (gidx < NB) ldj[gidx] = 0.f;
    if (gidx < MM) g_rrii[gidx] = Rs[(size_t)gidx * MM + gidx] * r2diag[gidx];
    #pragma unroll
    for (int l = 0; l < 2; l++) {
        int j = tid + l * 256;
        g_r1d [(size_t)row * MM + j] = (row <= j) ? Rs[(size_t)row * MM + j] : 0.f;
        g_r2Td[(size_t)row * MM + j] =
            (row > j) ? Rs[(size_t)j * MM + row] : ((row == j) ? r2diag[j] : 0.f);
    }
    if (row < HHN) {
        float a = v[row * ZS + tid], b = v[row * ZS + tid + 256];
        float s = a * a + b * b;
        #pragma unroll
        for (int o = 16; o > 0; o >>= 1) s += __shfl_xor_sync(0xffffffffu, s, o);
        __shared__ float ws[8];
        if ((tid & 31) == 0) ws[tid >> 5] = s;
        __syncthreads();
        float inv = rsqrtf(ws[0]+ws[1]+ws[2]+ws[3]+ws[4]+ws[5]+ws[6]+ws[7]);
        g_vn[row * ZS + tid] = a * inv;
        g_vn[row * ZS + tid + 256] = b * inv;
    } else if (row == HHN) {
        g_vn[row * ZS + tid] = 0.f;
        g_vn[row * ZS + tid + 256] = 0.f;
    }
}

// ---------------- WY T build ----------------
__global__ void tbuild_kernel() {
    __shared__ float cs[4][4];
    int tid = threadIdx.x, w = tid >> 5, lane = tid & 31, b = blockIdx.x;
    const int pi[6] = {0,0,0,1,1,2}, pj[6] = {1,2,3,2,3,3};
    if (w < 6) {
        const float* vi = g_vn + (size_t)(b * 4 + pi[w]) * ZS;
        const float* vj = g_vn + (size_t)(b * 4 + pj[w]) * ZS;
        float s = 0.f;
        #pragma unroll
        for (int t = 0; t < 16; t++) s += vi[lane + 32 * t] * vj[lane + 32 * t];
        #pragma unroll
        for (int o = 16; o > 0; o >>= 1) s += __shfl_xor_sync(0xffffffffu, s, o);
        if (lane == 0) cs[pi[w]][pj[w]] = s;
    }
    __syncthreads();
    if (tid == 0) {
        float T[4][4] = {};
        T[0][0] = T[1][1] = T[2][2] = T[3][3] = 2.f;
        for (int k = 1; k < 4; k++)
            for (int i = 0; i < k; i++) {
                float s = 0.f;
                for (int j = i; j < k; j++) s += T[i][j] * cs[j][k];
                T[i][k] = -2.f * s;
            }
        for (int i = 0; i < 4; i++)
            for (int k = 0; k < 4; k++) g_T[b * 16 + i * 4 + k] = T[i][k];
    }
}

// ---------------- fused: scan (blocks 0..63) + zsplit (blocks 64..) ----------------
__global__ void __launch_bounds__(128, 2) scan_zsplit_kernel(const float* __restrict__ z) {
    __shared__ float sv[2][4 * 512];
    __shared__ float Ts[2][16];
    int tid = threadIdx.x;
    if (blockIdx.x >= 64) {   // zsplit: fp32 -> fp16 hi/lo
        size_t u = (((size_t)(blockIdx.x - 64)) * 128 + tid) * 8;
        const float4* zp = (const float4*)(z + u);
        float4 a = zp[0], b = zp[1];
        float vs[8] = {a.x,a.y,a.z,a.w,b.x,b.y,b.z,b.w};
        half hi[8], lo[8];
        #pragma unroll
        for (int e = 0; e < 8; e++) {
            hi[e] = __float2half_rn(vs[e]);
            lo[e] = __float2half_rn(vs[e] - __half2float(hi[e]));
        }
        *(uint4*)&g_zhi[u] = *(uint4*)hi;
        *(uint4*)&g_zlo[u] = *(uint4*)lo;
        return;
    }
    int lane = tid & 31, warp = tid >> 5;
    int r0 = blockIdx.x * 8 + warp * 2;
    float f0[16], f1[16];
    #pragma unroll
    for (int j = 0; j < 16; j++) {
        int col = (j >> 2) * 128 + lane * 4 + (j & 3);
        f0[j] = (col == r0) ? 1.f : 0.f;
        f1[j] = (col == r0 + 1) ? 1.f : 0.f;
    }
    #pragma unroll
    for (int q = 0; q < 4; q++)
        *(float4*)&sv[0][(q * 128 + tid) * 4] = *(const float4*)&g_vn[(q * 128 + tid) * 4];
    if (tid < 16) Ts[0][tid] = g_T[tid];
    __syncthreads();

    for (int blk = 0; blk < 128; blk++) {
        int cur = blk & 1, nxt = cur ^ 1;
        float4 pf[4]; float tpf = 0.f;
        bool more = (blk + 1 < 128);
        if (more) {
            #pragma unroll
            for (int q = 0; q < 4; q++)
                pf[q] = *(const float4*)&g_vn[(size_t)(blk + 1) * 2048 + (q * 128 + tid) * 4];
            if (tid < 16) tpf = g_T[(blk + 1) * 16 + tid];
        }
        float vv[4][16];
        #pragma unroll
        for (int vb = 0; vb < 4; vb++)
            #pragma unroll
            for (int q = 0; q < 4; q++) {
                float4 t = *(const float4*)&sv[cur][vb * 512 + q * 128 + lane * 4];
                vv[vb][q*4+0] = t.x; vv[vb][q*4+1] = t.y; vv[vb][q*4+2] = t.z; vv[vb][q*4+3] = t.w;
            }
        float d0[4] = {}, d1[4] = {};
        #pragma unroll
        for (int vb = 0; vb < 4; vb++)
            #pragma unroll
            for (int j = 0; j < 16; j++) {
                d0[vb] = fmaf(f0[j], vv[vb][j], d0[vb]);
                d1[vb] = fmaf(f1[j], vv[vb][j], d1[vb]);
            }
        #pragma unroll
        for (int o = 16; o > 0; o >>= 1)
            #pragma unroll
            for (int vb = 0; vb < 4; vb++) {
                d0[vb] += __shfl_xor_sync(0xffffffffu, d0[vb], o);
                d1[vb] += __shfl_xor_sync(0xffffffffu, d1[vb], o);
            }
        float w0[4], w1[4];
        #pragma unroll
        for (int k = 0; k < 4; k++) {
            float s0 = 0.f, s1 = 0.f;
            #pragma unroll
            for (int i = 0; i < 4; i++) {
                if (i <= k) {
                    float t = Ts[cur][i * 4 + k];
                    s0 = fmaf(d0[i], t, s0);
                    s1 = fmaf(d1[i], t, s1);
                }
            }
            w0[k] = s0; w1[k] = s1;
        }
        #pragma unroll
        for (int j = 0; j < 16; j++) {
            float a0 = f0[j], a1 = f1[j];
            #pragma unroll
            for (int vb = 0; vb < 4; vb++) {
                a0 = fmaf(-w0[vb], vv[vb][j], a0);
                a1 = fmaf(-w1[vb], vv[vb][j], a1);
            }
            f0[j] = a0; f1[j] = a1;
        }
        if (more) {
            #pragma unroll
            for (int q = 0; q < 4; q++)
                *(float4*)&sv[nxt][(q * 128 + tid) * 4] = pf[q];
            if (tid < 16) Ts[nxt][tid] = tpf;
        }
        __syncthreads();
    }
    #pragma unroll
    for (int q = 0; q < 4; q++) {
        *(float4*)&g_q[(size_t)r0 * ZS + q * 128 + lane * 4] = make_float4(f0[q*4], f0[q*4+1], f0[q*4+2], f0[q*4+3]);
        *(float4*)&g_q[(size_t)(r0 + 1) * ZS + q * 128 + lane * 4] = make_float4(f1[q*4], f1[q*4+1], f1[q*4+2], f1[q*4+3]);
    }
}

// small GEMMs (dense, pipelined)
__global__ void __launch_bounds__(256) small_gemm_kernel() {
    __shared__ float Qs[2][16][68], Bs[2][16][68];
    int tid = threadIdx.x, tx = tid & 15, ty = tid >> 4;
    int j0 = blockIdx.x * 64, i0 = blockIdx.y * 64, mode = blockIdx.z;
    const float* Bsrc = mode ? g_r2Td : g_r1d;
    int qi = tid >> 2, qk = tid & 3;
    int bk = tid >> 4, bq = tid & 15;
    uint32_t bdst0 = smem_u32(&Bs[0][bk][bq * 4]);
    uint32_t bstride = (uint32_t)(sizeof(float) * 16 * 68);
    float acc[4][4] = {};

    float4 qv = *(const float4*)&g_q[(size_t)(i0 + qi) * ZS + qk * 4];
    cpa16(bdst0, Bsrc + (size_t)bk * MM + j0 + bq * 4);
    CP_COMMIT();
    Qs[0][qk*4+0][qi] = qv.x; Qs[0][qk*4+1][qi] = qv.y;
    Qs[0][qk*4+2][qi] = qv.z; Qs[0][qk*4+3][qi] = qv.w;

    for (int kt = 0; kt < 32; kt++) {
        int cur = kt & 1, nxt = cur ^ 1;
        bool more = (kt + 1 < 32);
        float4 qn;
        if (more)
            qn = *(const float4*)&g_q[(size_t)(i0 + qi) * ZS + (kt + 1) * 16 + qk * 4];
        CP_WAIT0();
        __syncthreads();
        if (more) {
            cpa16(bdst0 + nxt * bstride, Bsrc + (size_t)((kt + 1) * 16 + bk) * MM + j0 + bq * 4);
            CP_COMMIT();
        }
        #pragma unroll
        for (int kk = 0; kk < 16; kk++) {
            float4 a4 = *(const float4*)&Qs[cur][kk][ty * 4];
            float4 b4 = *(const float4*)&Bs[cur][kk][tx * 4];
            const float a[4] = {a4.x, a4.y, a4.z, a4.w};
            const float b[4] = {b4.x, b4.y, b4.z, b4.w};
            #pragma unroll
            for (int x = 0; x < 4; x++)
                #pragma unroll
                for (int y = 0; y < 4; y++) acc[x][y] = fmaf(a[x], b[y], acc[x][y]);
        }
        if (more) {
            Qs[nxt][qk*4+0][qi] = qn.x; Qs[nxt][qk*4+1][qi] = qn.y;
            Qs[nxt][qk*4+2][qi] = qn.z; Qs[nxt][qk*4+3][qi] = qn.w;
        }
    }
    #pragma unroll
    for (int x = 0; x < 4; x++)
        #pragma unroll
        for (int y = 0; y < 4; y++) {
            int i = i0 + ty*4 + x, j = j0 + tx*4 + y;
            float val = acc[x][y];
            half h = __float2half_rn(val);
            if (mode == 0) {
                g_Af[(size_t)i * MM + j] = h;
            } else {
                g_Bthi[(size_t)j * ZS + i] = h;
                g_Btlo[(size_t)j * ZS + i] = __float2half_rn(val - __half2float(h));
            }
        }
}

// ---------------- GEMM mainloops: CTA 128m x 256n, 8 warps 2m x 4n, warp 64x64 ----------------
// stage1 (48KB): Ah[0,8K) Al[8K,16K): slab*4096 + m*32;  Bh[16K,32K) Bl[32K,48K): slab*8192 + n*32
__device__ __forceinline__ void load_stage1(uint32_t sbuf,
    const half* __restrict__ Ah, const half* __restrict__ Al,
    const half* __restrict__ Bh, const half* __restrict__ Bl,
    int m0, int n0, int ch, int tid) {
    #pragma unroll
    for (int q = 0; q < 4; q++) {
        int idx = ((q & 1) << 8) + tid;
        int m = idx >> 2, cc2 = idx & 3;
        int slab = cc2 >> 1, hf = cc2 & 1;
        uint32_t dst = sbuf + (q >> 1) * 8192 + slab * 4096 + m * 32 + ((hf ^ ((m >> 2) & 1)) << 4);
        const half* base = (q < 2) ? Ah : Al;
        cpa16(dst, base + (size_t)(m0 + m) * 512 + ch * 32 + slab * 16 + hf * 8);
    }
    #pragma unroll
    for (int q = 0; q < 8; q++) {
        int idx = ((q & 3) << 8) + tid;
        int n = idx >> 2, cc2 = idx & 3;
        int slab = cc2 >> 1, hf = cc2 & 1;
        uint32_t dst = sbuf + 16384 + (q >> 2) * 16384 + slab * 8192 + n * 32 + ((hf ^ ((n >> 2) & 1)) << 4);
        const half* base = (q < 4) ? Bh : Bl;
        cpa16(dst, base + (size_t)(n0 + n) * 512 + ch * 32 + slab * 16 + hf * 8);
    }
}

__device__ __forceinline__ void mainloop3(float (&acc)[4][8][4],
    const half* __restrict__ Ah, const half* __restrict__ Al,
    const half* __restrict__ Bh, const half* __restrict__ Bl,
    int m0, int n0, uint32_t sb, int tid) {
    int lane = tid & 31, wid = tid >> 5;
    int wm = wid & 1, wn = wid >> 1;
    int arow = (lane & 7) + ((lane >> 3) & 1) * 8;
    int akh  = (lane >> 4) & 1;
    uint32_t aoff = (uint32_t)((wm * 64 + arow) * 32) + ((akh ^ ((arow >> 2) & 1)) << 4);
    int brow = (lane & 7) + ((lane >> 4) & 1) * 8;
    int bkh  = (lane >> 3) & 1;
    uint32_t boff = 16384u + (uint32_t)((wn * 64 + brow) * 32) + ((bkh ^ ((brow >> 2) & 1)) << 4);

    load_stage1(sb,        Ah, Al, Bh, Bl, m0, n0, 0, tid); CP_COMMIT();
    load_stage1(sb + STG1, Ah, Al, Bh, Bl, m0, n0, 1, tid); CP_COMMIT();

    for (int ch = 0; ch < 16; ch++) {
        CP_WAIT1();
        __syncthreads();
        if (ch + 2 < 16)
            load_stage1(sb + ((ch + 2) % 3) * STG1, Ah, Al, Bh, Bl, m0, n0, ch + 2, tid);
        CP_COMMIT();
        uint32_t st = sb + (ch % 3) * STG1;
        #pragma unroll
        for (int slab = 0; slab < 2; slab++) {
            uint32_t sA = st + slab * 4096 + aoff;
            uint32_t sBB = st + slab * 8192 + boff;
            uint32_t ah[4][4], bh[4][4], xx[4][4];
            #pragma unroll
            for (int p = 0; p < 4; p++) ldsm4(sA + p * 512, ah[p]);
            #pragma unroll
            for (int p = 0; p < 4; p++) ldsm4(sBB + p * 512, bh[p]);
            #pragma unroll
            for (int p = 0; p < 4; p++) ldsm4(sA + 8192 + p * 512, xx[p]);   // Al
            #pragma unroll
            for (int mt = 0; mt < 4; mt++)
                #pragma unroll
                for (int nt = 0; nt < 8; nt++)
                    mma16816(acc[mt][nt], ah[mt], &bh[nt >> 1][(nt & 1) * 2]);
            #pragma unroll
            for (int mt = 0; mt < 4; mt++)
                #pragma unroll
                for (int nt = 0; nt < 8; nt++)
                    mma16816(acc[mt][nt], xx[mt], &bh[nt >> 1][(nt & 1) * 2]);
            #pragma unroll
            for (int p = 0; p < 4; p++) ldsm4(sBB + 16384 + p * 512, xx[p]);  // Bl
            #pragma unroll
            for (int mt = 0; mt < 4; mt++)
                #pragma unroll
                for (int nt = 0; nt < 8; nt++)
                    mma16816(acc[mt][nt], ah[mt], &xx[nt >> 1][(nt & 1) * 2]);
        }
    }
}

// stage2 (24KB): A[0,8K): slab*4096 + m*32;  B[8K,24K): slab*8192 + n*32
__device__ __forceinline__ void load_stage2(uint32_t sbuf,
    const half* __restrict__ A, const half* __restrict__ B,
    int m0, int n0, int ch, int tid) {
    #pragma unroll
    for (int q = 0; q < 2; q++) {
        int idx = (q << 8) + tid;
        int m = idx >> 2, cc2 = idx & 3;
        int slab = cc2 >> 1, hf = cc2 & 1;
        uint32_t dst = sbuf + slab * 4096 + m * 32 + ((hf ^ ((m >> 2) & 1)) << 4);
        cpa16(dst, A + (size_t)(m0 + m) * 512 + ch * 32 + slab * 16 + hf * 8);
    }
    #pragma unroll
    for (int q = 0; q < 4; q++) {
        int idx = (q << 8) + tid;
        int n = idx >> 2, cc2 = idx & 3;
        int slab = cc2 >> 1, hf = cc2 & 1;
        uint32_t dst = sbuf + 8192 + slab * 8192 + n * 32 + ((hf ^ ((n >> 2) & 1)) << 4);
        cpa16(dst, B + (size_t)(n0 + n) * 512 + ch * 32 + slab * 16 + hf * 8);
    }
}

__device__ __forceinline__ void mainloop1(float (&acc)[4][8][4],
    const half* __restrict__ A, const half* __restrict__ B,
    int m0, int n0, uint32_t sb, int tid) {
    int lane = tid & 31, wid = tid >> 5;
    int wm = wid & 1, wn = wid >> 1;
    int arow = (lane & 7) + ((lane >> 3) & 1) * 8;
    int akh  = (lane >> 4) & 1;
    uint32_t aoff = (uint32_t)((wm * 64 + arow) * 32) + ((akh ^ ((arow >> 2) & 1)) << 4);
    int brow = (lane & 7) + ((lane >> 4) & 1) * 8;
    int bkh  = (lane >> 3) & 1;
    uint32_t boff = 8192u + (uint32_t)((wn * 64 + brow) * 32) + ((bkh ^ ((brow >> 2) & 1)) << 4);

    load_stage2(sb,            A, B, m0, n0, 0, tid); CP_COMMIT();
    load_stage2(sb + STG2,     A, B, m0, n0, 1, tid); CP_COMMIT();
    load_stage2(sb + 2 * STG2, A, B, m0, n0, 2, tid); CP_COMMIT();

    for (int ch = 0; ch < 16; ch++) {
        CP_WAIT2();
        __syncthreads();
        if (ch + 3 < 16) {
            load_stage2(sb + ((ch + 3) & 3) * STG2, A, B, m0, n0, ch + 3, tid);
            CP_COMMIT();
        }
        uint32_t st = sb + (ch & 3) * STG2;
        #pragma unroll
        for (int slab = 0; slab < 2; slab++) {
            uint32_t sA = st + slab * 4096 + aoff;
            uint32_t sBB = st + slab * 8192 + boff;
            uint32_t ah[4][4], bh[4][4];
            #pragma unroll
            for (int p = 0; p < 4; p++) ldsm4(sA + p * 512, ah[p]);
            #pragma unroll
            for (int p = 0; p < 4; p++) ldsm4(sBB + p * 512, bh[p]);
            #pragma unroll
            for (int mt = 0; mt < 4; mt++)
                #pragma unroll
                for (int nt = 0; nt < 8; nt++)
                    mma16816(acc[mt][nt], ah[mt], &bh[nt >> 1][(nt & 1) * 2]);
        }
    }
}

// GEMM1: hB = tanh(z@Bt + c), ldj, emit hB fp16
__global__ void __launch_bounds__(256, 1) gemm1_kernel(const float* __restrict__ c,
                                                       float* __restrict__ ldj) {
    extern __shared__ char smem[];
    uint32_t sb = smem_u32(smem);
    int tid = threadIdx.x, lane = tid & 31, wid = tid >> 5;
    int wm = wid & 1, wn = wid >> 1;
    int n0 = blockIdx.x * 256, m0 = blockIdx.y * 128;
    float acc[4][8][4] = {};
    mainloop3(acc, g_zhi, g_zlo, g_Bthi, g_Btlo, m0, n0, sb, tid);

    float cc[16], rr[16];
    #pragma unroll
    for (int nt = 0; nt < 8; nt++) {
        int col = n0 + wn * 64 + nt * 8 + (lane & 3) * 2;
        cc[nt*2] = c[col]; cc[nt*2+1] = c[col+1];
        rr[nt*2] = g_rrii[col]; rr[nt*2+1] = g_rrii[col+1];
    }
    #pragma unroll
    for (int mt = 0; mt < 4; mt++) {
        int row = m0 + wm * 64 + mt * 16 + (lane >> 2);
        float s0 = 0.f, s1 = 0.f;
        #pragma unroll
        for (int nt = 0; nt < 8; nt++) {
            int col = n0 + wn * 64 + nt * 8 + (lane & 3) * 2;
            float h00 = tanhf(acc[mt][nt][0] + cc[nt*2]);
            float h01 = tanhf(acc[mt][nt][1] + cc[nt*2+1]);
            float h10 = tanhf(acc[mt][nt][2] + cc[nt*2]);
            float h11 = tanhf(acc[mt][nt][3] + cc[nt*2+1]);
            *(half2*)&g_hbf[(size_t)row * MM + col]       = __floats2half2_rn(h00, h01);
            *(half2*)&g_hbf[(size_t)(row + 8) * MM + col] = __floats2half2_rn(h10, h11);
            s0 += __logf(fabsf(fmaf(1.f - h00*h00, rr[nt*2],   1.f)));
            s0 += __logf(fabsf(fmaf(1.f - h01*h01, rr[nt*2+1], 1.f)));
            s1 += __logf(fabsf(fmaf(1.f - h10*h10, rr[nt*2],   1.f)));
            s1 += __logf(fabsf(fmaf(1.f - h11*h11, rr[nt*2+1], 1.f)));
        }
        s0 += __shfl_xor_sync(0xffffffffu, s0, 1); s0 += __shfl_xor_sync(0xffffffffu, s0, 2);
        s1 += __shfl_xor_sync(0xffffffffu, s1, 1); s1 += __shfl_xor_sync(0xffffffffu, s1, 2);
        if ((lane & 3) == 0) {
            atomicAdd(&ldj[row], s0);
            atomicAdd(&ldj[row + 8], s1);
        }
    }
}

// GEMM2: out = hB @ A^T + z
__global__ void __launch_bounds__(256, 1) gemm2_kernel(const float* __restrict__ z,
                                                       float* __restrict__ out) {
    extern __shared__ char smem[];
    uint32_t sb = smem_u32(smem);
    int tid = threadIdx.x, lane = tid & 31, wid = tid >> 5;
    int wm = wid & 1, wn = wid >> 1;
    int n0 = blockIdx.x * 256, m0 = blockIdx.y * 128;
    float acc[4][8][4] = {};
    mainloop1(acc, g_hbf, g_Af, m0, n0, sb, tid);

    #pragma unroll
    for (int mt = 0; mt < 4; mt++) {
        int row = m0 + wm * 64 + mt * 16 + (lane >> 2);
        #pragma unroll
        for (int nt = 0; nt < 8; nt++) {
            int col = n0 + wn * 64 + nt * 8 + (lane & 3) * 2;
            float2 z0 = *(const float2*)&z[(size_t)row * ZS + col];
            float2 z1 = *(const float2*)&z[(size_t)(row + 8) * ZS + col];
            *(float2*)&out[(size_t)row * ZS + col] =
                make_float2(acc[mt][nt][0] + z0.x, acc[mt][nt][1] + z0.y);
            *(float2*)&out[(size_t)(row + 8) * ZS + col] =
                make_float2(acc[mt][nt][2] + z1.x, acc[mt][nt][3] + z1.y);
        }
    }
}

// ---------------- launch ----------------
extern "C" void kernel_launch(void* const* d_in, const int* in_sizes, int n_in,
                              void* d_out, int out_size) {
    const float* z      = (const float*)d_in[0];
    const float* v      = (const float*)d_in[1];
    const float* Rs     = (const float*)d_in[2];
    const float* r2diag = (const float*)d_in[3];
    const float* c      = (const float*)d_in[4];
    float* out = (float*)d_out;
    float* ldj = out + (size_t)NB * ZS;

    cudaFuncSetAttribute(gemm1_kernel, cudaFuncAttributeMaxDynamicSharedMemorySize, SMEM1);
    cudaFuncSetAttribute(gemm2_kernel, cudaFuncAttributeMaxDynamicSharedMemorySize, SMEM2);

    normalize_kernel<<<512, 256>>>(v, Rs, r2diag, ldj);
    tbuild_kernel<<<128, 192>>>();
    scan_zsplit_kernel<<<64 + (int)((size_t)NB * ZS / 1024), 128>>>(z);
    small_gemm_kernel<<<dim3(8, 8, 2), 256>>>();
    gemm1_kernel<<<dim3(2, 512), 256, SMEM1>>>(c, ldj);
    gemm2_kernel<<<dim3(2, 512), 256, SMEM2>>>(z, out);
}